// round 1
// baseline (speedup 1.0000x reference)
#include <cuda_runtime.h>
#include <math_constants.h>

// ---------------------------------------------------------------------------
// MultiTaskLossWrapper: two Cox losses + two pair-rank losses + scalar combine
// Inputs (metadata order):
//  0 hazard3d f32[B], 1 hazard1d f32[B], 2 survtime f32[B], 3 censor f32[B],
//  4 vars_ f32[4], 5 beta1 f32[1], 6 beta2 f32[1], 7 age i32[B], 8 grade i32[B]
// Output: f32[1]
// ---------------------------------------------------------------------------

#define BCAP 16384
#define ROWS_PER_BLOCK 8
#define THREADS 256

__constant__ float c_risk_table[9] = {1.0f, 1.0f, 0.91f, 1.12f, 1.71f,
                                      2.41f, 3.27f, 5.18f, 8.44f};

// per-row scratch (reduced by the finalize kernel)
__device__ float g_c3[BCAP];   // censor_i * (h3_i - logrisk3_i)
__device__ float g_c1[BCAP];   // censor_i * (h1_i - logrisk1_i)
__device__ float g_ls[BCAP];   // lgg partial sum for row i
__device__ float g_hs[BCAP];   // hgg partial sum for row i
__device__ float g_lc[BCAP];   // lgg pair count for row i
__device__ float g_hc[BCAP];   // hgg pair count for row i

__device__ __forceinline__ float warpSum(float v) {
#pragma unroll
    for (int o = 16; o; o >>= 1) v += __shfl_xor_sync(0xffffffffu, v, o);
    return v;
}
__device__ __forceinline__ float warpMax(float v) {
#pragma unroll
    for (int o = 16; o; o >>= 1) v = fmaxf(v, __shfl_xor_sync(0xffffffffu, v, o));
    return v;
}

__device__ __forceinline__ float softplusf(float x) {
    // log(1 + exp(x)), stable
    return fmaxf(x, 0.0f) + log1pf(__expf(-fabsf(x)));
}

__global__ void __launch_bounds__(THREADS)
row_kernel(const float* __restrict__ h3, const float* __restrict__ h1,
           const float* __restrict__ surv, const float* __restrict__ censor,
           const float* __restrict__ beta1p, const float* __restrict__ beta2p,
           const int* __restrict__ age, const int* __restrict__ grade, int B) {
    extern __shared__ float sm[];
    float* s_surv = sm;                 // [B]
    float* s_h3   = sm + B;             // [B]
    float* s_h1   = sm + 2 * B;         // [B]
    float* s_risk = sm + 3 * B;         // [B]
    unsigned char* s_flags = (unsigned char*)(sm + 4 * B);  // [B]

    const int tid = threadIdx.x;

    // cooperative load of everything into shared
    for (int j = tid; j < B; j += THREADS) {
        s_surv[j] = surv[j];
        s_h3[j]   = h3[j];
        s_h1[j]   = h1[j];
        int a = age[j];
        int g = grade[j];
        int b = a / 10; if (b > 8) b = 8; if (b < 0) b = 0;
        s_risk[j] = c_risk_table[b];
        bool g0  = (g == 0);
        bool g12 = (g == 1) || (g == 2);
        unsigned char f = 0;
        if (g0  && a >= 40) f |= 1;   // lgg "high" column candidate
        if (g12 && a >= 65) f |= 2;   // hgg "high" column candidate
        if (g0  && a < 40)  f |= 4;   // lgg "low"  row candidate
        if (g12 && a < 65)  f |= 8;   // hgg "low"  row candidate
        s_flags[j] = f;
    }
    __syncthreads();

    const float beta1 = *beta1p;
    const float beta2 = *beta2p;

    const int warp = tid >> 5;
    const int lane = tid & 31;
    const int i = blockIdx.x * ROWS_PER_BLOCK + warp;
    if (i >= B) return;

    const float surv_i = s_surv[i];
    const float h3_i   = s_h3[i];
    const float risk_i = s_risk[i];
    const unsigned char fi = s_flags[i];
    const bool lowL = (fi & 4) != 0;
    const bool lowH = (fi & 8) != 0;
    const bool anyPair = lowL || lowH;

    // pass 1: masked max for both hazards + pair-rank partial sums
    float m3 = -CUDART_INF_F, m1 = -CUDART_INF_F;
    float lsum = 0.f, hsum = 0.f, lcnt = 0.f, hcnt = 0.f;

    for (int j = lane; j < B; j += 32) {
        float sj = s_surv[j];
        if (sj >= surv_i) {
            m3 = fmaxf(m3, s_h3[j]);
            m1 = fmaxf(m1, s_h1[j]);
        }
        if (anyPair && j > i) {
            unsigned char fj = s_flags[j];
            float d  = (s_risk[j] - risk_i) * 0.125f;
            float dh = h3_i - s_h3[j];
            if (lowL && (fj & 1)) {
                float alpha = d / (1.0f + __expf(-beta1 * d));  // swish(d, beta1)
                lsum += softplusf(alpha * dh);
                lcnt += 1.0f;
            }
            if (lowH && (fj & 2)) {
                float alpha = d / (1.0f + __expf(-beta2 * d));  // swish(d, beta2)
                hsum += softplusf(alpha * dh);
                hcnt += 1.0f;
            }
        }
    }
    m3 = warpMax(m3);
    m1 = warpMax(m1);

    // pass 2: masked sum of exp
    float s3 = 0.f, s1 = 0.f;
    for (int j = lane; j < B; j += 32) {
        if (s_surv[j] >= surv_i) {
            s3 += __expf(s_h3[j] - m3);
            s1 += __expf(s_h1[j] - m1);
        }
    }
    s3 = warpSum(s3);
    s1 = warpSum(s1);
    lsum = warpSum(lsum);
    hsum = warpSum(hsum);
    lcnt = warpSum(lcnt);
    hcnt = warpSum(hcnt);

    if (lane == 0) {
        float lr3 = m3 + __logf(s3);
        float lr1 = m1 + __logf(s1);
        float ci = censor[i];
        g_c3[i] = ci * (h3_i - lr3);
        g_c1[i] = ci * (s_h1[i] - lr1);
        g_ls[i] = lsum;
        g_hs[i] = hsum;
        g_lc[i] = lcnt;
        g_hc[i] = hcnt;
    }
}

__global__ void __launch_bounds__(256)
final_kernel(const float* __restrict__ vars, float* __restrict__ out, int B) {
    __shared__ float red[6][8];
    const int tid = threadIdx.x;
    float a0 = 0.f, a1 = 0.f, a2 = 0.f, a3 = 0.f, a4 = 0.f, a5 = 0.f;
    for (int j = tid; j < B; j += 256) {
        a0 += g_c3[j];
        a1 += g_c1[j];
        a2 += g_ls[j];
        a3 += g_hs[j];
        a4 += g_lc[j];
        a5 += g_hc[j];
    }
    a0 = warpSum(a0); a1 = warpSum(a1); a2 = warpSum(a2);
    a3 = warpSum(a3); a4 = warpSum(a4); a5 = warpSum(a5);
    int lane = tid & 31, w = tid >> 5;
    if (lane == 0) {
        red[0][w] = a0; red[1][w] = a1; red[2][w] = a2;
        red[3][w] = a3; red[4][w] = a4; red[5][w] = a5;
    }
    __syncthreads();
    if (tid == 0) {
        float s0 = 0.f, s1 = 0.f, s2 = 0.f, s3 = 0.f, s4 = 0.f, s5 = 0.f;
#pragma unroll
        for (int w2 = 0; w2 < 8; w2++) {
            s0 += red[0][w2]; s1 += red[1][w2]; s2 += red[2][w2];
            s3 += red[3][w2]; s4 += red[4][w2]; s5 += red[5][w2];
        }
        float invB = 1.0f / (float)B;
        float loss3d = -s0 * invB;
        float loss1d = -s1 * invB;
        float lgg = (s4 > 0.5f) ? (s2 / s4) : 0.0f;
        float hgg = (s5 > 0.5f) ? (s3 / s5) : 0.0f;
        float losscli = lgg + hgg;
        float v0 = vars[0], v2 = vars[2], v3 = vars[3];
        float r = 0.5f * loss3d / (v0 * v0) + logf(v0)
                + 0.5f * loss1d / (v2 * v2) + logf(v2)
                + 0.5f * losscli / (v3 * v3) + logf(v3);
        out[0] = r;
    }
}

extern "C" void kernel_launch(void* const* d_in, const int* in_sizes, int n_in,
                              void* d_out, int out_size) {
    const float* h3     = (const float*)d_in[0];
    const float* h1     = (const float*)d_in[1];
    const float* surv   = (const float*)d_in[2];
    const float* censor = (const float*)d_in[3];
    const float* vars   = (const float*)d_in[4];
    const float* beta1  = (const float*)d_in[5];
    const float* beta2  = (const float*)d_in[6];
    const int*   age    = (const int*)d_in[7];
    const int*   grade  = (const int*)d_in[8];
    int B = in_sizes[0];

    size_t smem = (size_t)B * 4 * sizeof(float) + (size_t)B;  // 4 float arrays + flags
    cudaFuncSetAttribute(row_kernel, cudaFuncAttributeMaxDynamicSharedMemorySize,
                         (int)smem);

    int grid = (B + ROWS_PER_BLOCK - 1) / ROWS_PER_BLOCK;
    row_kernel<<<grid, THREADS, smem>>>(h3, h1, surv, censor, beta1, beta2,
                                        age, grade, B);
    final_kernel<<<1, 256>>>(vars, (float*)d_out, B);
}

// round 2
// speedup vs baseline: 2.3497x; 2.3497x over previous
#include <cuda_runtime.h>
#include <math_constants.h>

// ---------------------------------------------------------------------------
// MultiTaskLossWrapper: two Cox losses + two pair-rank losses + scalar combine
// Inputs (metadata order):
//  0 hazard3d f32[B], 1 hazard1d f32[B], 2 survtime f32[B], 3 censor f32[B],
//  4 vars_ f32[4], 5 beta1 f32[1], 6 beta2 f32[1], 7 age i32[B], 8 grade i32[B]
// Output: f32[1]
// ---------------------------------------------------------------------------

#define BMAX 8192
#define K1_THREADS 256
#define ROWS_PER_WARP 4
#define ROWS_PER_BLOCK 32           // 8 warps * 4 rows
#define MAX_COX_BLOCKS 512          // ceil(BMAX/32) = 256 max, headroom
#define K2_BLOCKS 512
#define K2_THREADS 128
#define TILE 128

__constant__ float c_risk_table[9] = {1.0f, 1.0f, 0.91f, 1.12f, 1.71f,
                                      2.41f, 3.27f, 5.18f, 8.44f};

// scratch (device globals; no allocation anywhere)
__device__ float2 g_cox_part[MAX_COX_BLOCKS];
__device__ float4 g_pair_part[K2_BLOCKS];
__device__ int    g_cnt[4] = {0, 0, 0, 0};   // lowL, highL, lowH, highH; K3 re-zeros
__device__ int    g_meta[4][BMAX];           // (orig_idx<<4) | bucket
__device__ float  g_h[4][BMAX];              // hazard3d value

__device__ __forceinline__ float warpSum(float v) {
#pragma unroll
    for (int o = 16; o; o >>= 1) v += __shfl_xor_sync(0xffffffffu, v, o);
    return v;
}
__device__ __forceinline__ float warpMax(float v) {
#pragma unroll
    for (int o = 16; o; o >>= 1) v = fmaxf(v, __shfl_xor_sync(0xffffffffu, v, o));
    return v;
}

// ===========================================================================
// K1: Cox partial sums (block handles 32 rows) + list compaction
// ===========================================================================
__global__ void __launch_bounds__(K1_THREADS)
cox_kernel(const float* __restrict__ h3, const float* __restrict__ h1,
           const float* __restrict__ surv, const float* __restrict__ censor,
           const int* __restrict__ age, const int* __restrict__ grade, int B) {
    extern __shared__ float4 sp[];   // [B]: (surv, exp(h3-M3), exp(h1-M1), 0)
    __shared__ float red[16];

    const int tid  = threadIdx.x;
    const int w    = tid >> 5;
    const int lane = tid & 31;

    // --- global maxes -----------------------------------------------------
    float m3 = -CUDART_INF_F, m1 = -CUDART_INF_F;
    for (int j = tid; j < B; j += K1_THREADS) {
        m3 = fmaxf(m3, h3[j]);
        m1 = fmaxf(m1, h1[j]);
    }
    m3 = warpMax(m3); m1 = warpMax(m1);
    if (lane == 0) { red[w] = m3; red[8 + w] = m1; }
    __syncthreads();
    float M3 = -CUDART_INF_F, M1 = -CUDART_INF_F;
#pragma unroll
    for (int k = 0; k < 8; k++) { M3 = fmaxf(M3, red[k]); M1 = fmaxf(M1, red[8 + k]); }
    __syncthreads();

    // --- fill packed shared -----------------------------------------------
    for (int j = tid; j < B; j += K1_THREADS) {
        sp[j] = make_float4(surv[j], __expf(h3[j] - M3), __expf(h1[j] - M1), 0.0f);
    }
    __syncthreads();

    // --- per-warp: 4 rows, lanes stride columns ---------------------------
    const int r0 = blockIdx.x * ROWS_PER_BLOCK + w * ROWS_PER_WARP;
    float si[ROWS_PER_WARP];
    float s3[ROWS_PER_WARP], s1[ROWS_PER_WARP];
#pragma unroll
    for (int k = 0; k < ROWS_PER_WARP; k++) {
        int r = r0 + k;
        si[k] = (r < B) ? sp[r].x : CUDART_INF_F;
        s3[k] = 0.0f; s1[k] = 0.0f;
    }
    for (int j = lane; j < B; j += 32) {
        float4 p = sp[j];
#pragma unroll
        for (int k = 0; k < ROWS_PER_WARP; k++) {
            bool m = (p.x >= si[k]);
            s3[k] += m ? p.y : 0.0f;
            s1[k] += m ? p.z : 0.0f;
        }
    }
    float c3 = 0.0f, c1 = 0.0f;
#pragma unroll
    for (int k = 0; k < ROWS_PER_WARP; k++) {
        s3[k] = warpSum(s3[k]);
        s1[k] = warpSum(s1[k]);
        if (lane == 0) {
            int r = r0 + k;
            if (r < B) {
                float ci = censor[r];
                c3 += ci * (h3[r] - M3 - __logf(s3[k]));
                c1 += ci * (h1[r] - M1 - __logf(s1[k]));
            }
        }
    }
    __shared__ float cred[16];
    if (lane == 0) { cred[w] = c3; cred[8 + w] = c1; }
    __syncthreads();
    if (tid == 0) {
        float a = 0.0f, b = 0.0f;
#pragma unroll
        for (int k = 0; k < 8; k++) { a += cred[k]; b += cred[8 + k]; }
        g_cox_part[blockIdx.x] = make_float2(a, b);
    }

    // --- compaction: warp 0 handles this block's 32 elements --------------
    if (w == 0) {
        int e = blockIdx.x * ROWS_PER_BLOCK + lane;
        bool valid = (e < B);
        int a_ = valid ? age[e]   : -1;
        int g_ = valid ? grade[e] : -1;
        bool g0  = (g_ == 0);
        bool g12 = (g_ == 1) || (g_ == 2);
        int bkt = a_ / 10; if (bkt > 8) bkt = 8; if (bkt < 0) bkt = 0;
        float hv = valid ? h3[e] : 0.0f;
        int meta = (e << 4) | bkt;
        bool pred[4];
        pred[0] = valid && g0  && (a_ < 40);
        pred[1] = valid && g0  && (a_ >= 40);
        pred[2] = valid && g12 && (a_ < 65);
        pred[3] = valid && g12 && (a_ >= 65);
#pragma unroll
        for (int l = 0; l < 4; l++) {
            unsigned mask = __ballot_sync(0xffffffffu, pred[l]);
            if (mask) {
                int base = 0;
                if (lane == 0) base = atomicAdd(&g_cnt[l], __popc(mask));
                base = __shfl_sync(0xffffffffu, base, 0);
                if (pred[l]) {
                    int pos = base + __popc(mask & ((1u << lane) - 1u));
                    g_meta[l][pos] = meta;
                    g_h[l][pos]    = hv;
                }
            }
        }
    }
}

// ===========================================================================
// K2: pair-rank losses over compacted lists (tiled, grid-stride)
// ===========================================================================
__global__ void __launch_bounds__(K2_THREADS)
pair_kernel(const float* __restrict__ beta1p, const float* __restrict__ beta2p) {
    __shared__ float tabL[81], tabH[81];
    __shared__ int   smeta[TILE];
    __shared__ float sh[TILE];
    __shared__ float redS[8];

    const int tid = threadIdx.x;

    if (tid < 81) {
        float b1 = *beta1p, b2 = *beta2p;
        int bi = tid / 9, bj = tid % 9;
        float d = (c_risk_table[bj] - c_risk_table[bi]) * 0.125f;
        tabL[tid] = d / (1.0f + __expf(-b1 * d));
        tabH[tid] = d / (1.0f + __expf(-b2 * d));
    }

    const int nLL = g_cnt[0], nHL = g_cnt[1], nLH = g_cnt[2], nHH = g_cnt[3];
    const int tlL = (nLL + TILE - 1) / TILE, thL = (nHL + TILE - 1) / TILE;
    const int tlH = (nLH + TILE - 1) / TILE, thH = (nHH + TILE - 1) / TILE;
    const int TL = tlL * thL;
    const int T  = TL + tlH * thH;

    float accS0 = 0.0f, accC0 = 0.0f, accS1 = 0.0f, accC1 = 0.0f;
    __syncthreads();  // tables visible

    for (int t = blockIdx.x; t < T; t += gridDim.x) {
        int prob, lt, ht, nLow, nHigh, llist, hlist;
        if (t < TL) { prob = 0; lt = t / thL; ht = t - lt * thL;
                      nLow = nLL; nHigh = nHL; llist = 0; hlist = 1; }
        else        { int tt = t - TL; prob = 1; lt = tt / thH; ht = tt - lt * thH;
                      nLow = nLH; nHigh = nHH; llist = 2; hlist = 3; }

        int j0 = ht * TILE;
        int hcount = nHigh - j0; if (hcount > TILE) hcount = TILE;

        __syncthreads();  // previous tile's smem reads done
        if (tid < hcount) {
            smeta[tid] = g_meta[hlist][j0 + tid];
            sh[tid]    = g_h[hlist][j0 + tid];
        }
        __syncthreads();

        int li = lt * TILE + tid;
        if (li < nLow) {
            int mi = g_meta[llist][li];
            int idxi = mi >> 4;
            const float* tab = prob ? tabH : tabL;
            int rowoff = (mi & 15) * 9;
            float hi = g_h[llist][li];
            float s = 0.0f, c = 0.0f;
            for (int jj = 0; jj < hcount; jj++) {
                int mj = smeta[jj];
                if ((mj >> 4) > idxi) {
                    float alpha = tab[rowoff + (mj & 15)];
                    float x = alpha * (hi - sh[jj]);
                    float e = __expf(-fabsf(x));
                    s += fmaxf(x, 0.0f) + __logf(1.0f + e);
                    c += 1.0f;
                }
            }
            if (prob == 0) { accS0 += s; accC0 += c; }
            else           { accS1 += s; accC1 += c; }
        }
    }

    // block reduce 4 accumulators (4 warps)
    const int w = tid >> 5, lane = tid & 31;
    float4 v = make_float4(warpSum(accS0), warpSum(accC0),
                           warpSum(accS1), warpSum(accC1));
    __syncthreads();
    if (lane == 0) {
        redS[w]     = v.x;  redS[4 + w] = v.y;
    }
    __shared__ float redS2[8];
    if (lane == 1) {
        redS2[w]     = 0.0f;  // placeholder, overwritten below
    }
    __syncthreads();
    // second pair of accumulators via a second pass to keep smem small
    __shared__ float redT[8];
    if (lane == 0) { redT[w] = v.z; redT[4 + w] = v.w; }
    __syncthreads();
    if (tid == 0) {
        float a = 0.0f, b = 0.0f, cS = 0.0f, d = 0.0f;
#pragma unroll
        for (int k = 0; k < 4; k++) {
            a  += redS[k]; b += redS[4 + k];
            cS += redT[k]; d += redT[4 + k];
        }
        g_pair_part[blockIdx.x] = make_float4(a, b, cS, d);
    }
}

// ===========================================================================
// K3: final reduce + combine; re-zero compaction counters for next replay
// ===========================================================================
__global__ void __launch_bounds__(256)
final_kernel(const float* __restrict__ vars, float* __restrict__ out,
             int B, int nCoxBlocks) {
    __shared__ float red[6][8];
    const int tid = threadIdx.x;
    float a0 = 0.f, a1 = 0.f, a2 = 0.f, a3 = 0.f, a4 = 0.f, a5 = 0.f;
    for (int i = tid; i < nCoxBlocks; i += 256) {
        float2 p = g_cox_part[i];
        a0 += p.x; a1 += p.y;
    }
    for (int i = tid; i < K2_BLOCKS; i += 256) {
        float4 p = g_pair_part[i];
        a2 += p.x; a3 += p.y; a4 += p.z; a5 += p.w;
    }
    a0 = warpSum(a0); a1 = warpSum(a1); a2 = warpSum(a2);
    a3 = warpSum(a3); a4 = warpSum(a4); a5 = warpSum(a5);
    const int lane = tid & 31, w = tid >> 5;
    if (lane == 0) {
        red[0][w] = a0; red[1][w] = a1; red[2][w] = a2;
        red[3][w] = a3; red[4][w] = a4; red[5][w] = a5;
    }
    __syncthreads();
    if (tid < 4) g_cnt[tid] = 0;   // reset for next launch/replay
    if (tid == 0) {
        float s0 = 0.f, s1 = 0.f, s2 = 0.f, s3 = 0.f, s4 = 0.f, s5 = 0.f;
#pragma unroll
        for (int k = 0; k < 8; k++) {
            s0 += red[0][k]; s1 += red[1][k]; s2 += red[2][k];
            s3 += red[3][k]; s4 += red[4][k]; s5 += red[5][k];
        }
        float invB = 1.0f / (float)B;
        float loss3d = -s0 * invB;
        float loss1d = -s1 * invB;
        float lgg = (s3 > 0.5f) ? (s2 / s3) : 0.0f;
        float hgg = (s5 > 0.5f) ? (s4 / s5) : 0.0f;
        float losscli = lgg + hgg;
        float v0 = vars[0], v2 = vars[2], v3 = vars[3];
        out[0] = 0.5f * loss3d / (v0 * v0) + logf(v0)
               + 0.5f * loss1d / (v2 * v2) + logf(v2)
               + 0.5f * losscli / (v3 * v3) + logf(v3);
    }
}

extern "C" void kernel_launch(void* const* d_in, const int* in_sizes, int n_in,
                              void* d_out, int out_size) {
    const float* h3     = (const float*)d_in[0];
    const float* h1     = (const float*)d_in[1];
    const float* surv   = (const float*)d_in[2];
    const float* censor = (const float*)d_in[3];
    const float* vars   = (const float*)d_in[4];
    const float* beta1  = (const float*)d_in[5];
    const float* beta2  = (const float*)d_in[6];
    const int*   age    = (const int*)d_in[7];
    const int*   grade  = (const int*)d_in[8];
    int B = in_sizes[0];

    size_t smem = (size_t)B * sizeof(float4);
    cudaFuncSetAttribute(cox_kernel, cudaFuncAttributeMaxDynamicSharedMemorySize,
                         (int)smem);

    int nCoxBlocks = (B + ROWS_PER_BLOCK - 1) / ROWS_PER_BLOCK;
    cox_kernel<<<nCoxBlocks, K1_THREADS, smem>>>(h3, h1, surv, censor, age, grade, B);
    pair_kernel<<<K2_BLOCKS, K2_THREADS>>>(beta1, beta2);
    final_kernel<<<1, 256>>>(vars, (float*)d_out, B, nCoxBlocks);
}

// round 3
// speedup vs baseline: 2.3741x; 1.0104x over previous
#include <cuda_runtime.h>
#include <math_constants.h>

// ---------------------------------------------------------------------------
// MultiTaskLossWrapper: two Cox losses + two pair-rank losses + scalar combine
// Inputs: 0 hazard3d f32[B], 1 hazard1d f32[B], 2 survtime f32[B],
//         3 censor f32[B], 4 vars_ f32[4], 5 beta1, 6 beta2,
//         7 age i32[B], 8 grade i32[B].  Output: f32[1]
// ---------------------------------------------------------------------------

#define BMAX 8192
#define NPAIR 160
#define LOWTILE 256
#define HITILE 128

__constant__ float c_risk_table[9] = {1.0f, 1.0f, 0.91f, 1.12f, 1.71f,
                                      2.41f, 3.27f, 5.18f, 8.44f};

// device-global scratch (no allocations anywhere, no atomics anywhere)
__device__ float4 g_sp[BMAX];        // (surv, exp(h3-M3), exp(h1-M1), censor)
__device__ int    g_cnt[4];          // list sizes (overwritten every call)
__device__ int    g_meta[4][BMAX];   // (orig_idx<<4) | decade_bucket
__device__ float  g_hlist[4][BMAX];  // hazard3d
__device__ float2 g_cox_part[512];
__device__ float4 g_pair_part[512];

__device__ __forceinline__ float warpSum(float v) {
#pragma unroll
    for (int o = 16; o; o >>= 1) v += __shfl_xor_sync(0xffffffffu, v, o);
    return v;
}
__device__ __forceinline__ float warpMax(float v) {
#pragma unroll
    for (int o = 16; o; o >>= 1) v = fmaxf(v, __shfl_xor_sync(0xffffffffu, v, o));
    return v;
}

// ===========================================================================
// PREP: single block. Global maxes, packed sp[], deterministic list build.
// ===========================================================================
__global__ void __launch_bounds__(1024)
prep_kernel(const float* __restrict__ h3, const float* __restrict__ h1,
            const float* __restrict__ surv, const float* __restrict__ censor,
            const int* __restrict__ age, const int* __restrict__ grade, int B) {
    __shared__ float red[64];
    __shared__ int warpbase[4][32];
    __shared__ int listbase[4];

    const int tid = threadIdx.x;
    const int w = tid >> 5;
    const int lane = tid & 31;

    // global maxes of h3, h1
    float m3 = -CUDART_INF_F, m1 = -CUDART_INF_F;
    for (int j = tid; j < B; j += 1024) {
        m3 = fmaxf(m3, h3[j]);
        m1 = fmaxf(m1, h1[j]);
    }
    m3 = warpMax(m3); m1 = warpMax(m1);
    if (lane == 0) { red[w] = m3; red[32 + w] = m1; }
    if (tid < 4 && tid >= 0) listbase[tid] = 0;
    __syncthreads();
    if (w == 0) { float v = warpMax(red[lane]); if (lane == 0) red[0] = v; }
    if (w == 1) { float v = warpMax(red[32 + lane]); if (lane == 0) red[32] = v; }
    __syncthreads();
    const float M3 = red[0];
    const float M1 = red[32];

    const int passes = (B + 1023) / 1024;
    for (int p = 0; p < passes; p++) {
        int e = p * 1024 + tid;
        bool valid = (e < B);

        float hv = 0.0f;
        int a_ = -1, g_ = -1, meta = 0;
        if (valid) {
            float sv = surv[e];
            float v3 = h3[e];
            float v1 = h1[e];
            float cv = censor[e];
            g_sp[e] = make_float4(sv, __expf(v3 - M3), __expf(v1 - M1), cv);
            hv = v3;
            a_ = age[e];
            g_ = grade[e];
            int bkt = a_ / 10; if (bkt > 8) bkt = 8; if (bkt < 0) bkt = 0;
            meta = (e << 4) | bkt;
        }
        bool g0  = (g_ == 0);
        bool g12 = (g_ == 1) || (g_ == 2);
        bool pred[4];
        pred[0] = valid && g0  && (a_ < 40);   // lgg low
        pred[1] = valid && g0  && (a_ >= 40);  // lgg high
        pred[2] = valid && g12 && (a_ < 65);   // hgg low
        pred[3] = valid && g12 && (a_ >= 65);  // hgg high

        unsigned mk[4];
#pragma unroll
        for (int l = 0; l < 4; l++) {
            mk[l] = __ballot_sync(0xffffffffu, pred[l]);
            if (lane == 0) warpbase[l][w] = __popc(mk[l]);
        }
        __syncthreads();
        // deterministic exclusive scan of 32 warp counts, per list (warps 0-3)
        if (w < 4) {
            int l = w;
            int c = warpbase[l][lane];
            int x = c;
#pragma unroll
            for (int o = 1; o < 32; o <<= 1) {
                int y = __shfl_up_sync(0xffffffffu, x, o);
                if (lane >= o) x += y;
            }
            int excl = x - c;
            int base = listbase[l];
            warpbase[l][lane] = base + excl;
            if (lane == 31) listbase[l] = base + excl + c;
        }
        __syncthreads();
#pragma unroll
        for (int l = 0; l < 4; l++) {
            if (pred[l]) {
                int pos = warpbase[l][w] + __popc(mk[l] & ((1u << lane) - 1u));
                g_meta[l][pos]  = meta;
                g_hlist[l][pos] = hv;
            }
        }
        __syncthreads();  // protect warpbase/listbase for next pass
    }
    if (tid < 4) g_cnt[tid] = listbase[tid];
}

// ===========================================================================
// MAIN: fused cox (blocks [0,nCox)) + pair-rank (blocks [nCox, nCox+NPAIR))
// ===========================================================================
__global__ void __launch_bounds__(256)
main_kernel(const float* __restrict__ beta1p, const float* __restrict__ beta2p,
            int B, int nCox) {
    __shared__ float sred[16];
    __shared__ float tabL[81], tabH[81];
    __shared__ int   smeta[HITILE];
    __shared__ float shh[HITILE];

    const int tid = threadIdx.x;
    const int w = tid >> 5;
    const int lane = tid & 31;

    if ((int)blockIdx.x < nCox) {
        // ------------------- Cox part: 32 rows/block, 4 rows/warp ---------
        const int r0 = blockIdx.x * 32 + w * 4;
        float si[4], e3s[4], cens[4], le3[4];
        float s3[4], s1[4];
#pragma unroll
        for (int k = 0; k < 4; k++) {
            int r = r0 + k;
            float4 q = (r < B) ? g_sp[r]
                               : make_float4(CUDART_INF_F, 1.0f, 1.0f, 0.0f);
            si[k] = q.x; e3s[k] = q.y; le3[k] = q.z; cens[k] = q.w;
            s3[k] = 0.0f; s1[k] = 0.0f;
        }
        const float4* __restrict__ sp = g_sp;
#pragma unroll 4
        for (int j = lane; j < B; j += 32) {
            float4 p = __ldg(&sp[j]);
#pragma unroll
            for (int k = 0; k < 4; k++) {
                if (p.x >= si[k]) { s3[k] += p.y; s1[k] += p.z; }
            }
        }
        float c3 = 0.0f, c1 = 0.0f;
#pragma unroll
        for (int k = 0; k < 4; k++) {
            s3[k] = warpSum(s3[k]);
            s1[k] = warpSum(s1[k]);
            if (lane == 0 && (r0 + k) < B) {
                c3 += cens[k] * __logf(__fdividef(e3s[k], s3[k]));
                c1 += cens[k] * __logf(__fdividef(le3[k], s1[k]));
            }
        }
        if (lane == 0) { sred[w] = c3; sred[8 + w] = c1; }
        __syncthreads();
        if (tid == 0) {
            float a = 0.0f, b = 0.0f;
#pragma unroll
            for (int k = 0; k < 8; k++) { a += sred[k]; b += sred[8 + k]; }
            g_cox_part[blockIdx.x] = make_float2(a, b);
        }
    } else {
        // ------------------- pair-rank part --------------------------------
        const int pb = blockIdx.x - nCox;
        const int gridP = gridDim.x - nCox;

        if (tid < 81) {
            float b1 = *beta1p, b2 = *beta2p;
            int bi = tid / 9, bj = tid % 9;
            float d = (c_risk_table[bj] - c_risk_table[bi]) * 0.125f;
            tabL[tid] = d / (1.0f + __expf(-b1 * d));
            tabH[tid] = d / (1.0f + __expf(-b2 * d));
        }

        const int nLL = g_cnt[0], nHL = g_cnt[1], nLH = g_cnt[2], nHH = g_cnt[3];
        const int tlL = (nLL + LOWTILE - 1) / LOWTILE;
        const int thL = (nHL + HITILE - 1) / HITILE;
        const int tlH = (nLH + LOWTILE - 1) / LOWTILE;
        const int thH = (nHH + HITILE - 1) / HITILE;
        const int TL = tlL * thL;
        const int T  = TL + tlH * thH;

        float accS0 = 0.0f, accC0 = 0.0f, accS1 = 0.0f, accC1 = 0.0f;
        __syncthreads();  // tables ready

        for (int t = pb; t < T; t += gridP) {
            int prob, lt, ht, nLow, nHigh, llist, hlist;
            if (t < TL) { prob = 0; lt = t / thL; ht = t - lt * thL;
                          nLow = nLL; nHigh = nHL; llist = 0; hlist = 1; }
            else        { int tt = t - TL; prob = 1; lt = tt / thH; ht = tt - lt * thH;
                          nLow = nLH; nHigh = nHH; llist = 2; hlist = 3; }

            int j0 = ht * HITILE;
            int hcount = nHigh - j0; if (hcount > HITILE) hcount = HITILE;

            __syncthreads();
            if (tid < hcount) {
                smeta[tid] = g_meta[hlist][j0 + tid];
                shh[tid]   = g_hlist[hlist][j0 + tid];
            }
            __syncthreads();

            int li = lt * LOWTILE + tid;
            if (li < nLow) {
                int mi = g_meta[llist][li];
                int idxi = mi >> 4;
                const float* tab = prob ? tabH : tabL;
                int rowoff = (mi & 15) * 9;
                float hi = g_hlist[llist][li];
                float s = 0.0f, c = 0.0f;
                for (int jj = 0; jj < hcount; jj++) {
                    int mj = smeta[jj];
                    if ((mj >> 4) > idxi) {
                        float alpha = tab[rowoff + (mj & 15)];
                        float x = alpha * (hi - shh[jj]);
                        float e = __expf(-fabsf(x));
                        s += fmaxf(x, 0.0f) + __logf(1.0f + e);
                        c += 1.0f;
                    }
                }
                if (prob == 0) { accS0 += s; accC0 += c; }
                else           { accS1 += s; accC1 += c; }
            }
        }

        accS0 = warpSum(accS0); accC0 = warpSum(accC0);
        accS1 = warpSum(accS1); accC1 = warpSum(accC1);
        __syncthreads();
        __shared__ float pr[4][8];
        if (lane == 0) {
            pr[0][w] = accS0; pr[1][w] = accC0;
            pr[2][w] = accS1; pr[3][w] = accC1;
        }
        __syncthreads();
        if (tid == 0) {
            float a = 0.f, b = 0.f, c = 0.f, d = 0.f;
#pragma unroll
            for (int k = 0; k < 8; k++) {
                a += pr[0][k]; b += pr[1][k]; c += pr[2][k]; d += pr[3][k];
            }
            g_pair_part[pb] = make_float4(a, b, c, d);
        }
    }
}

// ===========================================================================
// FINAL: reduce partials + scalar combine
// ===========================================================================
__global__ void __launch_bounds__(256)
final_kernel(const float* __restrict__ vars, float* __restrict__ out,
             int B, int nCox) {
    __shared__ float red[6][8];
    const int tid = threadIdx.x;
    float a0 = 0.f, a1 = 0.f, a2 = 0.f, a3 = 0.f, a4 = 0.f, a5 = 0.f;
    for (int i = tid; i < nCox; i += 256) {
        float2 p = g_cox_part[i];
        a0 += p.x; a1 += p.y;
    }
    for (int i = tid; i < NPAIR; i += 256) {
        float4 p = g_pair_part[i];
        a2 += p.x; a3 += p.y; a4 += p.z; a5 += p.w;
    }
    a0 = warpSum(a0); a1 = warpSum(a1); a2 = warpSum(a2);
    a3 = warpSum(a3); a4 = warpSum(a4); a5 = warpSum(a5);
    const int lane = tid & 31, w = tid >> 5;
    if (lane == 0) {
        red[0][w] = a0; red[1][w] = a1; red[2][w] = a2;
        red[3][w] = a3; red[4][w] = a4; red[5][w] = a5;
    }
    __syncthreads();
    if (tid == 0) {
        float s0 = 0.f, s1 = 0.f, s2 = 0.f, s3 = 0.f, s4 = 0.f, s5 = 0.f;
#pragma unroll
        for (int k = 0; k < 8; k++) {
            s0 += red[0][k]; s1 += red[1][k]; s2 += red[2][k];
            s3 += red[3][k]; s4 += red[4][k]; s5 += red[5][k];
        }
        float invB = 1.0f / (float)B;
        float loss3d = -s0 * invB;
        float loss1d = -s1 * invB;
        float lgg = (s3 > 0.5f) ? (s2 / s3) : 0.0f;
        float hgg = (s5 > 0.5f) ? (s4 / s5) : 0.0f;
        float losscli = lgg + hgg;
        float v0 = vars[0], v2 = vars[2], v3 = vars[3];
        out[0] = 0.5f * loss3d / (v0 * v0) + logf(v0)
               + 0.5f * loss1d / (v2 * v2) + logf(v2)
               + 0.5f * losscli / (v3 * v3) + logf(v3);
    }
}

extern "C" void kernel_launch(void* const* d_in, const int* in_sizes, int n_in,
                              void* d_out, int out_size) {
    const float* h3     = (const float*)d_in[0];
    const float* h1     = (const float*)d_in[1];
    const float* surv   = (const float*)d_in[2];
    const float* censor = (const float*)d_in[3];
    const float* vars   = (const float*)d_in[4];
    const float* beta1  = (const float*)d_in[5];
    const float* beta2  = (const float*)d_in[6];
    const int*   age    = (const int*)d_in[7];
    const int*   grade  = (const int*)d_in[8];
    int B = in_sizes[0];

    int nCox = (B + 31) / 32;
    prep_kernel<<<1, 1024>>>(h3, h1, surv, censor, age, grade, B);
    main_kernel<<<nCox + NPAIR, 256>>>(beta1, beta2, B, nCox);
    final_kernel<<<1, 256>>>(vars, (float*)d_out, B, nCox);
}